// round 3
// baseline (speedup 1.0000x reference)
#include <cuda_runtime.h>

#define T_SEQ 8192
#define C_DIM 64
#define B_SZ 2
#define L_CH 64
#define NCH (T_SEQ / L_CH)       /* 128 chunks per batch */
#define NCHT (B_SZ * NCH)        /* 256 chunks total     */
#define SP 68                    /* padded smem row stride (floats) */
#define TPB 256
#define GAMMA_D 0.96875
#define TILE_F (C_DIM * SP)      /* 4352 floats per padded 64x64 tile */

/* scratch: per-chunk decayed KV sums and per-chunk start states (4 MB each) */
__device__ float g_A[NCHT * C_DIM * C_DIM];
__device__ float g_S[NCHT * C_DIM * C_DIM];

/* ---------------- Kernel A: per-chunk K,V projection + decayed KV outer sum ---- */
__global__ __launch_bounds__(TPB) void kchunkA(const float* __restrict__ Xin,
                                               const float* __restrict__ WK,
                                               const float* __restrict__ WV) {
    extern __shared__ float sm[];
    float* sX  = sm;
    float* sWK = sm + 1 * TILE_F;
    float* sWV = sm + 2 * TILE_F;
    float* sK  = sm + 3 * TILE_F;   /* holds gamma^(63-i) * K[i][:] */
    float* sV  = sm + 4 * TILE_F;
    float* sgp = sm + 5 * TILE_F;   /* gamma powers 0..64 */

    const int tid = threadIdx.x;
    const int blk = blockIdx.x;           /* 0..255 */
    const int b = blk >> 7, ci = blk & 127;
    const float* Xg = Xin + (size_t)(b * T_SEQ + ci * L_CH) * C_DIM;

    for (int e = tid; e < 1024; e += TPB) {
        int r = e >> 4, c4 = (e & 15) << 2;
        *(float4*)(sX  + r * SP + c4) = *(const float4*)(Xg + r * 64 + c4);
        *(float4*)(sWK + r * SP + c4) = *(const float4*)(WK + r * 64 + c4);
        *(float4*)(sWV + r * SP + c4) = *(const float4*)(WV + r * 64 + c4);
    }
    if (tid == 0) {
        double g = 1.0;
        for (int n = 0; n <= 64; ++n) { sgp[n] = (float)g; g *= GAMMA_D; }
    }
    __syncthreads();

    const int r = tid >> 2, q = tid & 3, c0 = q << 4;

    /* K,V projections for this 64-row tile */
    {
        float aK[16], aV[16];
        #pragma unroll
        for (int cc = 0; cc < 16; ++cc) { aK[cc] = 0.f; aV[cc] = 0.f; }
        for (int k = 0; k < 64; ++k) {
            float x = sX[r * SP + k];
            const float* wk = sWK + k * SP + c0;
            const float* wv = sWV + k * SP + c0;
            #pragma unroll
            for (int cc = 0; cc < 16; ++cc) {
                aK[cc] += x * wk[cc];
                aV[cc] += x * wv[cc];
            }
        }
        float wgt = sgp[63 - r];   /* fold decay weight into K rows */
        #pragma unroll
        for (int cc = 0; cc < 16; ++cc) {
            sK[r * SP + c0 + cc] = aK[cc] * wgt;
            sV[r * SP + c0 + cc] = aV[cc];
        }
    }
    __syncthreads();

    /* A[p][c] = sum_i Kw[i][p] * V[i][c] */
    {
        const int p = r;
        float acc[16];
        #pragma unroll
        for (int cc = 0; cc < 16; ++cc) acc[cc] = 0.f;
        for (int i = 0; i < 64; ++i) {
            float kp = sK[i * SP + p];
            const float* vr = sV + i * SP + c0;
            #pragma unroll
            for (int cc = 0; cc < 16; ++cc) acc[cc] += kp * vr[cc];
        }
        float* Ag = g_A + blk * 4096 + p * 64 + c0;
        #pragma unroll
        for (int c4 = 0; c4 < 16; c4 += 4)
            *(float4*)(Ag + c4) = make_float4(acc[c4], acc[c4+1], acc[c4+2], acc[c4+3]);
    }
}

/* ---------------- Kernel B: scan over chunks (per state element) --------------- */
__global__ __launch_bounds__(TPB) void kscan() {
    const int e = blockIdx.x * TPB + threadIdx.x;   /* 0..8191 */
    const int b = e >> 12, idx = e & 4095;
    double gd = 1.0;
    #pragma unroll
    for (int n = 0; n < 64; ++n) gd *= GAMMA_D;
    const float d64 = (float)gd;

    const float* Ab = g_A + (size_t)b * NCH * 4096 + idx;
    float*       Sb = g_S + (size_t)b * NCH * 4096 + idx;
    float s = 0.f;
    for (int c = 0; c < NCH; c += 8) {
        float a[8];
        #pragma unroll
        for (int j = 0; j < 8; ++j) a[j] = Ab[(size_t)(c + j) * 4096];
        #pragma unroll
        for (int j = 0; j < 8; ++j) {
            Sb[(size_t)(c + j) * 4096] = s;     /* state at chunk start */
            s = s * d64 + a[j];
        }
    }
}

/* ---- Kernel C: per-chunk QKV proj + intra P·V + cross Q·S + GroupNorm + store - */
__global__ __launch_bounds__(TPB) void kchunkC(const float* __restrict__ Xin,
                                               const float* __restrict__ WQ,
                                               const float* __restrict__ WKg,
                                               const float* __restrict__ WVg,
                                               const float* __restrict__ gnw,
                                               const float* __restrict__ gnb,
                                               float* __restrict__ Out) {
    extern __shared__ float sm[];
    float* sX  = sm;                 /* Q_in tile; later raw out buffer     */
    float* sW0 = sm + 1 * TILE_F;    /* WQ; later S                          */
    float* sW1 = sm + 2 * TILE_F;    /* WK; later P                          */
    float* sW2 = sm + 3 * TILE_F;    /* WV; later transposed normalized out  */
    float* sQ  = sm + 4 * TILE_F;
    float* sK  = sm + 5 * TILE_F;
    float* sV  = sm + 6 * TILE_F;
    float* sgp = sm + 7 * TILE_F;    /* 72 */
    float* sgw = sgp + 72;           /* 64 */
    float* sgb = sgw + 64;           /* 64 */

    const int tid = threadIdx.x;
    const int blk = blockIdx.x;
    const int b = blk >> 7, ci = blk & 127;
    const int t0 = ci * L_CH;
    const float* Xg = Xin + (size_t)(b * T_SEQ + t0) * C_DIM;

    for (int e = tid; e < 1024; e += TPB) {
        int r = e >> 4, c4 = (e & 15) << 2;
        *(float4*)(sX  + r * SP + c4) = *(const float4*)(Xg  + r * 64 + c4);
        *(float4*)(sW0 + r * SP + c4) = *(const float4*)(WQ  + r * 64 + c4);
        *(float4*)(sW1 + r * SP + c4) = *(const float4*)(WKg + r * 64 + c4);
        *(float4*)(sW2 + r * SP + c4) = *(const float4*)(WVg + r * 64 + c4);
    }
    if (tid < 64) { sgw[tid] = gnw[tid]; sgb[tid] = gnb[tid]; }
    if (tid == 0) {
        double g = 1.0;
        for (int n = 0; n <= 64; ++n) { sgp[n] = (float)g; g *= GAMMA_D; }
    }
    __syncthreads();

    const int r = tid >> 2, q = tid & 3, c0 = q << 4;

    /* projections -> sQ, sK, sV */
    {
        float* dst[3]  = { sQ, sK, sV };
        float* wsrc[3] = { sW0, sW1, sW2 };
        #pragma unroll
        for (int m = 0; m < 3; ++m) {
            float acc[16];
            #pragma unroll
            for (int cc = 0; cc < 16; ++cc) acc[cc] = 0.f;
            const float* W = wsrc[m];
            for (int k = 0; k < 64; ++k) {
                float x = sX[r * SP + k];
                const float* wr = W + k * SP + c0;
                #pragma unroll
                for (int cc = 0; cc < 16; ++cc) acc[cc] += x * wr[cc];
            }
            float* D = dst[m] + r * SP + c0;
            #pragma unroll
            for (int cc = 0; cc < 16; ++cc) D[cc] = acc[cc];
        }
    }
    __syncthreads();

    /* load S (state at chunk start) into sW0; compute masked P into sW1 */
    float* sS = sW0;
    float* sP = sW1;
    for (int e = tid; e < 1024; e += TPB) {
        int rr = e >> 4, c4 = (e & 15) << 2;
        *(float4*)(sS + rr * SP + c4) = *(const float4*)(g_S + blk * 4096 + rr * 64 + c4);
    }
    {
        const int i = r;
        float acc[16];
        #pragma unroll
        for (int jj = 0; jj < 16; ++jj) acc[jj] = 0.f;
        for (int k0 = 0; k0 < 64; k0 += 4) {
            float4 qv = *(const float4*)(sQ + i * SP + k0);
            #pragma unroll
            for (int jj = 0; jj < 16; ++jj) {
                int j = q + (jj << 2);                      /* stride-4: LDS conflict-free */
                float4 kv = *(const float4*)(sK + j * SP + k0);
                acc[jj] += qv.x * kv.x + qv.y * kv.y + qv.z * kv.z + qv.w * kv.w;
            }
        }
        #pragma unroll
        for (int jj = 0; jj < 16; ++jj) {
            int j = q + (jj << 2);
            float d = (i >= j) ? sgp[i - j] : 0.f;
            sP[i * SP + j] = acc[jj] * d;
        }
    }
    __syncthreads();

    /* out[i][c] = sum_j P[i][j] V[j][c] + gamma^(i+1) * sum_k Q[i][k] S[k][c] */
    float* sRaw = sX;
    {
        const int i = r;
        float o1[16], o2[16];
        #pragma unroll
        for (int cc = 0; cc < 16; ++cc) { o1[cc] = 0.f; o2[cc] = 0.f; }
        for (int j = 0; j < 64; ++j) {
            float pij = sP[i * SP + j];
            const float* vr = sV + j * SP + q;
            #pragma unroll
            for (int cc = 0; cc < 16; ++cc) o1[cc] += pij * vr[cc << 2];
        }
        for (int k = 0; k < 64; ++k) {
            float qk = sQ[i * SP + k];
            const float* sr = sS + k * SP + q;
            #pragma unroll
            for (int cc = 0; cc < 16; ++cc) o2[cc] += qk * sr[cc << 2];
        }
        float ge = sgp[i + 1];
        #pragma unroll
        for (int cc = 0; cc < 16; ++cc)
            sRaw[i * SP + q + (cc << 2)] = o1[cc] + ge * o2[cc];
    }
    __syncthreads();

    /* GroupNorm: each thread owns row r, 16 contiguous channels = 2 full groups. */
    float* sOT = sW2;   /* transposed normalized out: [c][i], stride SP */
    {
        const int i = r;
        const float* row = sRaw + i * SP + c0;
        #pragma unroll
        for (int g2 = 0; g2 < 2; ++g2) {
            float x[8]; float sum = 0.f, sq = 0.f;
            #pragma unroll
            for (int u = 0; u < 8; ++u) {
                x[u] = row[g2 * 8 + u];
                sum += x[u]; sq += x[u] * x[u];
            }
            float mu  = sum * 0.125f;
            float var = sq * 0.125f - mu * mu;     /* biased, matches GroupNorm */
            float inv = rsqrtf(var + 1e-6f);
            #pragma unroll
            for (int u = 0; u < 8; ++u) {
                int c = c0 + g2 * 8 + u;
                sOT[c * SP + i] = (x[u] - mu) * inv * sgw[c] + sgb[c];
            }
        }
    }
    __syncthreads();

    /* permuted store: Out[b*C*T + c*T + t0 + i]  (the swapaxes+view epilogue) */
    {
        float* Ob = Out + (size_t)b * C_DIM * T_SEQ + t0;
        for (int e = tid; e < 1024; e += TPB) {
            int c = e >> 4, i4 = (e & 15) << 2;
            float4 v = *(const float4*)(sOT + c * SP + i4);
            *(float4*)(Ob + (size_t)c * T_SEQ + i4) = v;
        }
    }
}

extern "C" void kernel_launch(void* const* d_in, const int* in_sizes, int n_in,
                              void* d_out, int out_size) {
    const float* Q_in = (const float*)d_in[0];
    const float* W_Q  = (const float*)d_in[1];
    const float* W_K  = (const float*)d_in[2];
    const float* W_V  = (const float*)d_in[3];
    const float* gnw  = (const float*)d_in[4];
    const float* gnb  = (const float*)d_in[5];
    float* out = (float*)d_out;

    const int smemA = (5 * TILE_F + 72) * (int)sizeof(float);            /* 87328  */
    const int smemC = (7 * TILE_F + 72 + 128) * (int)sizeof(float);      /* 122656 */
    cudaFuncSetAttribute(kchunkA, cudaFuncAttributeMaxDynamicSharedMemorySize, smemA);
    cudaFuncSetAttribute(kchunkC, cudaFuncAttributeMaxDynamicSharedMemorySize, smemC);

    kchunkA<<<NCHT, TPB, smemA>>>(Q_in, W_K, W_V);
    kscan<<<32, TPB>>>();
    kchunkC<<<NCHT, TPB, smemC>>>(Q_in, W_Q, W_K, W_V, gnw, gnb, out);
}

// round 5
// speedup vs baseline: 3.3729x; 3.3729x over previous
#include <cuda_runtime.h>

#define T_SEQ 8192
#define C_DIM 64
#define B_SZ 2
#define L_CH 64
#define NCH (T_SEQ / L_CH)       /* 128 chunks per batch */
#define NCHT (B_SZ * NCH)        /* 256 chunks total     */
#define SP 68                    /* padded smem row stride (floats) */
#define TPB 256
#define GAMMA_D 0.96875
#define TILE_F (C_DIM * SP)      /* 4352 floats per padded 64x64 tile */

/* L2-resident scratch (20 MB): per-chunk Q, K^T, V, decayed-KV sums, start states */
__device__ float g_Q [NCHT * 4096];
__device__ float g_Kt[NCHT * 4096];
__device__ float g_V [NCHT * 4096];
__device__ float g_A [NCHT * 4096];
__device__ float g_S [NCHT * 4096];

/* ---- Kernel A: QKV projection (4x4 reg tiles) + decayed KV outer sum ---------- */
__global__ __launch_bounds__(TPB, 3) void kchunkA(const float* __restrict__ Xin,
                                                  const float* __restrict__ WQ,
                                                  const float* __restrict__ WK,
                                                  const float* __restrict__ WV) {
    extern __shared__ float sm[];
    float* sX  = sm;
    float* sW0 = sm + 1 * TILE_F;
    float* sW1 = sm + 2 * TILE_F;
    float* sW2 = sm + 3 * TILE_F;
    float* sgp = sm + 4 * TILE_F;   /* gamma powers 0..64 */

    const int tid = threadIdx.x;
    const int blk = blockIdx.x;            /* 0..255 */
    const int b = blk >> 7, ci = blk & 127;
    const float* Xg = Xin + (size_t)(b * T_SEQ + ci * L_CH) * C_DIM;

    for (int e = tid; e < 1024; e += TPB) {
        int r = e >> 4, c4 = (e & 15) << 2;
        *(float4*)(sX  + r * SP + c4) = *(const float4*)(Xg + r * 64 + c4);
        *(float4*)(sW0 + r * SP + c4) = *(const float4*)(WQ + r * 64 + c4);
        *(float4*)(sW1 + r * SP + c4) = *(const float4*)(WK + r * 64 + c4);
        *(float4*)(sW2 + r * SP + c4) = *(const float4*)(WV + r * 64 + c4);
    }
    if (tid == 0) {
        double g = 1.0;
        for (int n = 0; n <= 64; ++n) { sgp[n] = (float)g; g *= GAMMA_D; }
    }
    __syncthreads();

    const int ty = tid >> 4, tx = tid & 15;
    const int r0 = ty << 2, c0 = tx << 2;

    float aQ[16], aK[16], aV[16];
    #pragma unroll
    for (int u = 0; u < 16; ++u) { aQ[u] = 0.f; aK[u] = 0.f; aV[u] = 0.f; }

    #pragma unroll 4
    for (int k = 0; k < 64; ++k) {
        float x[4];
        #pragma unroll
        for (int m = 0; m < 4; ++m) x[m] = sX[(r0 + m) * SP + k];
        float4 wq = *(float4*)(sW0 + k * SP + c0);
        float4 wk = *(float4*)(sW1 + k * SP + c0);
        float4 wv = *(float4*)(sW2 + k * SP + c0);
        #pragma unroll
        for (int m = 0; m < 4; ++m) {
            aQ[m*4+0] += x[m]*wq.x; aQ[m*4+1] += x[m]*wq.y;
            aQ[m*4+2] += x[m]*wq.z; aQ[m*4+3] += x[m]*wq.w;
            aK[m*4+0] += x[m]*wk.x; aK[m*4+1] += x[m]*wk.y;
            aK[m*4+2] += x[m]*wk.z; aK[m*4+3] += x[m]*wk.w;
            aV[m*4+0] += x[m]*wv.x; aV[m*4+1] += x[m]*wv.y;
            aV[m*4+2] += x[m]*wv.z; aV[m*4+3] += x[m]*wv.w;
        }
    }

    /* spill Q (row-major), K^T ([p][i], full-sector STG.128), V (row-major) */
    {
        float* Qg = g_Q  + blk * 4096;
        float* Kg = g_Kt + blk * 4096;
        float* Vg = g_V  + blk * 4096;
        #pragma unroll
        for (int m = 0; m < 4; ++m) {
            *(float4*)(Qg + (r0+m)*64 + c0) = make_float4(aQ[m*4], aQ[m*4+1], aQ[m*4+2], aQ[m*4+3]);
            *(float4*)(Vg + (r0+m)*64 + c0) = make_float4(aV[m*4], aV[m*4+1], aV[m*4+2], aV[m*4+3]);
        }
        #pragma unroll
        for (int n = 0; n < 4; ++n)
            *(float4*)(Kg + (c0+n)*64 + r0) = make_float4(aK[n], aK[4+n], aK[8+n], aK[12+n]);
    }
    __syncthreads();   /* all reads of sX/sW done; safe to alias */

    /* decayed K and V into smem (alias tiles 0,1) */
    float* sKd = sm;
    float* sVv = sm + TILE_F;
    #pragma unroll
    for (int m = 0; m < 4; ++m) {
        float w = sgp[63 - (r0 + m)];
        *(float4*)(sKd + (r0+m)*SP + c0) = make_float4(aK[m*4]*w, aK[m*4+1]*w, aK[m*4+2]*w, aK[m*4+3]*w);
        *(float4*)(sVv + (r0+m)*SP + c0) = make_float4(aV[m*4], aV[m*4+1], aV[m*4+2], aV[m*4+3]);
    }
    __syncthreads();

    /* A[p][c] = sum_i Kd[i][p] V[i][c] */
    float acc[16];
    #pragma unroll
    for (int u = 0; u < 16; ++u) acc[u] = 0.f;
    #pragma unroll 4
    for (int i = 0; i < 64; ++i) {
        float kd[4];
        #pragma unroll
        for (int m = 0; m < 4; ++m) kd[m] = sKd[i * SP + r0 + m];
        float4 v = *(float4*)(sVv + i * SP + c0);
        #pragma unroll
        for (int m = 0; m < 4; ++m) {
            acc[m*4+0] += kd[m]*v.x; acc[m*4+1] += kd[m]*v.y;
            acc[m*4+2] += kd[m]*v.z; acc[m*4+3] += kd[m]*v.w;
        }
    }
    float* Ag = g_A + blk * 4096;
    #pragma unroll
    for (int m = 0; m < 4; ++m)
        *(float4*)(Ag + (r0+m)*64 + c0) = make_float4(acc[m*4], acc[m*4+1], acc[m*4+2], acc[m*4+3]);
}

/* ---------------- Kernel B: scan over chunks (per state element) --------------- */
__global__ __launch_bounds__(TPB) void kscan() {
    const int e = blockIdx.x * TPB + threadIdx.x;   /* 0..8191 */
    const int b = e >> 12, idx = e & 4095;
    double gd = 1.0;
    #pragma unroll
    for (int n = 0; n < 64; ++n) gd *= GAMMA_D;
    const float d64 = (float)gd;

    const float* Ab = g_A + (size_t)b * NCH * 4096 + idx;
    float*       Sb = g_S + (size_t)b * NCH * 4096 + idx;
    float s = 0.f;
    for (int c = 0; c < NCH; c += 8) {
        float a[8];
        #pragma unroll
        for (int j = 0; j < 8; ++j) a[j] = Ab[(size_t)(c + j) * 4096];
        #pragma unroll
        for (int j = 0; j < 8; ++j) {
            Sb[(size_t)(c + j) * 4096] = s;     /* state at chunk start */
            s = s * d64 + a[j];
        }
    }
}

/* ---- Kernel C: P=Q·K^T (masked), out = P·V + diag(gamma)·Q·S, GN, perm store -- */
__global__ __launch_bounds__(TPB, 3) void kchunkC(const float* __restrict__ gnw,
                                                  const float* __restrict__ gnb,
                                                  float* __restrict__ Out) {
    extern __shared__ float sm[];
    float* sQ  = sm;
    float* sKt = sm + 1 * TILE_F;   /* later reused as sP */
    float* sV  = sm + 2 * TILE_F;
    float* sS  = sm + 3 * TILE_F;
    float* sgp = sm + 4 * TILE_F;

    const int tid = threadIdx.x;
    const int blk = blockIdx.x;
    const int b = blk >> 7, t0 = (blk & 127) << 6;

    const float* Qg = g_Q  + blk * 4096;
    const float* Kg = g_Kt + blk * 4096;
    const float* Vg = g_V  + blk * 4096;
    const float* Sg = g_S  + blk * 4096;

    for (int e = tid; e < 1024; e += TPB) {
        int r = e >> 4, c4 = (e & 15) << 2;
        *(float4*)(sQ  + r * SP + c4) = *(const float4*)(Qg + r * 64 + c4);
        *(float4*)(sKt + r * SP + c4) = *(const float4*)(Kg + r * 64 + c4);
        *(float4*)(sV  + r * SP + c4) = *(const float4*)(Vg + r * 64 + c4);
        *(float4*)(sS  + r * SP + c4) = *(const float4*)(Sg + r * 64 + c4);
    }
    if (tid == 0) {
        double g = 1.0;
        for (int n = 0; n <= 64; ++n) { sgp[n] = (float)g; g *= GAMMA_D; }
    }
    __syncthreads();

    const int ty = tid >> 4, tx = tid & 15;
    const int r0 = ty << 2, c0 = tx << 2;

    const float4 gw4 = *(const float4*)(gnw + c0);
    const float4 gb4 = *(const float4*)(gnb + c0);

    /* P[i][j] = sum_k Q[i][k] Kt[k][j], masked by decay */
    float p[16];
    #pragma unroll
    for (int u = 0; u < 16; ++u) p[u] = 0.f;
    #pragma unroll 4
    for (int k = 0; k < 64; ++k) {
        float q[4];
        #pragma unroll
        for (int m = 0; m < 4; ++m) q[m] = sQ[(r0 + m) * SP + k];
        float4 kt = *(float4*)(sKt + k * SP + c0);
        #pragma unroll
        for (int m = 0; m < 4; ++m) {
            p[m*4+0] += q[m]*kt.x; p[m*4+1] += q[m]*kt.y;
            p[m*4+2] += q[m]*kt.z; p[m*4+3] += q[m]*kt.w;
        }
    }
    #pragma unroll
    for (int m = 0; m < 4; ++m)
        #pragma unroll
        for (int n = 0; n < 4; ++n) {
            int i = r0 + m, j = c0 + n;
            p[m*4+n] = (i >= j) ? p[m*4+n] * sgp[i - j] : 0.f;
        }
    __syncthreads();                  /* all reads of sKt done */
    float* sP = sKt;
    #pragma unroll
    for (int m = 0; m < 4; ++m)
        *(float4*)(sP + (r0+m)*SP + c0) = make_float4(p[m*4], p[m*4+1], p[m*4+2], p[m*4+3]);
    __syncthreads();

    /* out = P·V + gamma^(i+1) · Q·S */
    float o1[16], o2[16];
    #pragma unroll
    for (int u = 0; u < 16; ++u) { o1[u] = 0.f; o2[u] = 0.f; }
    #pragma unroll 2
    for (int j = 0; j < 64; ++j) {
        float pm[4], qm[4];
        #pragma unroll
        for (int m = 0; m < 4; ++m) {
            pm[m] = sP[(r0 + m) * SP + j];
            qm[m] = sQ[(r0 + m) * SP + j];
        }
        float4 v = *(float4*)(sV + j * SP + c0);
        float4 s = *(float4*)(sS + j * SP + c0);
        #pragma unroll
        for (int m = 0; m < 4; ++m) {
            o1[m*4+0] += pm[m]*v.x; o1[m*4+1] += pm[m]*v.y;
            o1[m*4+2] += pm[m]*v.z; o1[m*4+3] += pm[m]*v.w;
            o2[m*4+0] += qm[m]*s.x; o2[m*4+1] += qm[m]*s.y;
            o2[m*4+2] += qm[m]*s.z; o2[m*4+3] += qm[m]*s.w;
        }
    }

    float o[16];
    #pragma unroll
    for (int m = 0; m < 4; ++m) {
        float ge = sgp[r0 + m + 1];
        #pragma unroll
        for (int n = 0; n < 4; ++n) o[m*4+n] = o1[m*4+n] + ge * o2[m*4+n];
    }

    /* GroupNorm: thread's 4 channels + lane-partner's 4 = one 8-channel group */
    const float gwv[4] = { gw4.x, gw4.y, gw4.z, gw4.w };
    const float gbv[4] = { gb4.x, gb4.y, gb4.z, gb4.w };
    #pragma unroll
    for (int m = 0; m < 4; ++m) {
        float s_ = o[m*4] + o[m*4+1] + o[m*4+2] + o[m*4+3];
        float q_ = o[m*4]*o[m*4] + o[m*4+1]*o[m*4+1] + o[m*4+2]*o[m*4+2] + o[m*4+3]*o[m*4+3];
        s_ += __shfl_xor_sync(0xffffffffu, s_, 1);
        q_ += __shfl_xor_sync(0xffffffffu, q_, 1);
        float mu  = s_ * 0.125f;
        float var = q_ * 0.125f - mu * mu;      /* biased, matches GroupNorm */
        float inv = rsqrtf(var + 1e-6f);
        #pragma unroll
        for (int n = 0; n < 4; ++n)
            o[m*4+n] = (o[m*4+n] - mu) * inv * gwv[n] + gbv[n];
    }

    /* permuted store Out[b][c][t]: per channel, 4 consecutive t as STG.128 */
    float* Ob = Out + (size_t)b * C_DIM * T_SEQ + t0 + r0;
    #pragma unroll
    for (int n = 0; n < 4; ++n)
        *(float4*)(Ob + (size_t)(c0 + n) * T_SEQ) = make_float4(o[n], o[4+n], o[8+n], o[12+n]);
}

extern "C" void kernel_launch(void* const* d_in, const int* in_sizes, int n_in,
                              void* d_out, int out_size) {
    const float* Q_in = (const float*)d_in[0];
    const float* W_Q  = (const float*)d_in[1];
    const float* W_K  = (const float*)d_in[2];
    const float* W_V  = (const float*)d_in[3];
    const float* gnw  = (const float*)d_in[4];
    const float* gnb  = (const float*)d_in[5];
    float* out = (float*)d_out;

    const int smemA = (4 * TILE_F + 72) * (int)sizeof(float);   /* 69920 B */
    const int smemC = (4 * TILE_F + 72) * (int)sizeof(float);   /* 69920 B */
    cudaFuncSetAttribute(kchunkA, cudaFuncAttributeMaxDynamicSharedMemorySize, smemA);
    cudaFuncSetAttribute(kchunkC, cudaFuncAttributeMaxDynamicSharedMemorySize, smemC);

    kchunkA<<<NCHT, TPB, smemA>>>(Q_in, W_Q, W_K, W_V);
    kscan<<<32, TPB>>>();
    kchunkC<<<NCHT, TPB, smemC>>>(gnw, gnb, out);
}

// round 6
// speedup vs baseline: 3.5110x; 1.0409x over previous
#include <cuda_runtime.h>

#define T_SEQ 8192
#define C_DIM 64
#define B_SZ 2
#define L_CH 64
#define NCH (T_SEQ / L_CH)       /* 128 chunks per batch */
#define NCHT (B_SZ * NCH)        /* 256 chunks total     */
#define SP 68                    /* padded smem row stride (floats); 272B = 16B-aligned rows */
#define TPB 256
#define GAMMA_D 0.96875
#define TILE_F (C_DIM * SP)      /* 4352 floats per padded 64x64 tile */

typedef unsigned long long ull;

/* ---- packed f32x2 helpers (sm_103a 2xFP32 pipe; exact RN, bit-identical) ------ */
__device__ __forceinline__ ull bc2(float x) {
    ull r; asm("mov.b64 %0, {%1, %1};" : "=l"(r) : "f"(x)); return r;
}
__device__ __forceinline__ void fma2(ull& a, ull b, ull c) {
    asm("fma.rn.f32x2 %0, %1, %2, %0;" : "+l"(a) : "l"(b), "l"(c));
}
__device__ __forceinline__ float2 up2(ull v) {
    float2 r; asm("mov.b64 {%0, %1}, %2;" : "=f"(r.x), "=f"(r.y) : "l"(v)); return r;
}

/* L2-resident scratch: per-chunk Q, K^T, V, decayed-KV sums, start states */
__device__ float g_Q [NCHT * 4096];
__device__ float g_Kt[NCHT * 4096];
__device__ float g_V [NCHT * 4096];
__device__ float g_A [NCHT * 4096];
__device__ float g_S [NCHT * 4096];

/* ---- Kernel A: QKV projection (4x4 reg tiles, f32x2) + decayed KV outer sum --- */
__global__ __launch_bounds__(TPB, 3) void kchunkA(const float* __restrict__ Xin,
                                                  const float* __restrict__ WQ,
                                                  const float* __restrict__ WK,
                                                  const float* __restrict__ WV) {
    extern __shared__ float sm[];
    float* sX  = sm;
    float* sW0 = sm + 1 * TILE_F;
    float* sW1 = sm + 2 * TILE_F;
    float* sW2 = sm + 3 * TILE_F;
    float* sgp = sm + 4 * TILE_F;   /* gamma powers 0..64 */

    const int tid = threadIdx.x;
    const int blk = blockIdx.x;            /* 0..255 */
    const int b = blk >> 7, ci = blk & 127;
    const float* Xg = Xin + (size_t)(b * T_SEQ + ci * L_CH) * C_DIM;

    for (int e = tid; e < 1024; e += TPB) {
        int r = e >> 4, c4 = (e & 15) << 2;
        *(float4*)(sX  + r * SP + c4) = *(const float4*)(Xg + r * 64 + c4);
        *(float4*)(sW0 + r * SP + c4) = *(const float4*)(WQ + r * 64 + c4);
        *(float4*)(sW1 + r * SP + c4) = *(const float4*)(WK + r * 64 + c4);
        *(float4*)(sW2 + r * SP + c4) = *(const float4*)(WV + r * 64 + c4);
    }
    if (tid == 0) {
        double g = 1.0;
        for (int n = 0; n <= 64; ++n) { sgp[n] = (float)g; g *= GAMMA_D; }
    }
    __syncthreads();

    const int ty = tid >> 4, tx = tid & 15;
    const int r0 = ty << 2, c0 = tx << 2;

    /* accumulators as packed pairs: [m] x {cols c0..c0+1, c0+2..c0+3} */
    ull q01[4], q23[4], k01[4], k23[4], v01[4], v23[4];
    #pragma unroll
    for (int m = 0; m < 4; ++m) {
        q01[m]=0ull; q23[m]=0ull; k01[m]=0ull; k23[m]=0ull; v01[m]=0ull; v23[m]=0ull;
    }

    #pragma unroll 4
    for (int k = 0; k < 64; ++k) {
        ull xb[4];
        #pragma unroll
        for (int m = 0; m < 4; ++m) xb[m] = bc2(sX[(r0 + m) * SP + k]);
        ulonglong2 wq = *(const ulonglong2*)(sW0 + k * SP + c0);
        ulonglong2 wk = *(const ulonglong2*)(sW1 + k * SP + c0);
        ulonglong2 wv = *(const ulonglong2*)(sW2 + k * SP + c0);
        #pragma unroll
        for (int m = 0; m < 4; ++m) {
            fma2(q01[m], xb[m], wq.x); fma2(q23[m], xb[m], wq.y);
            fma2(k01[m], xb[m], wk.x); fma2(k23[m], xb[m], wk.y);
            fma2(v01[m], xb[m], wv.x); fma2(v23[m], xb[m], wv.y);
        }
    }

    /* unpack K,V to scalars (needed for transpose + decay) */
    float kf[16], vf[16];
    #pragma unroll
    for (int m = 0; m < 4; ++m) {
        float2 a = up2(k01[m]), bb = up2(k23[m]);
        kf[m*4+0]=a.x; kf[m*4+1]=a.y; kf[m*4+2]=bb.x; kf[m*4+3]=bb.y;
        float2 c = up2(v01[m]), d = up2(v23[m]);
        vf[m*4+0]=c.x; vf[m*4+1]=c.y; vf[m*4+2]=d.x; vf[m*4+3]=d.y;
    }

    /* spill Q (row-major), K^T ([p][i]), V (row-major) */
    {
        float* Qg = g_Q  + blk * 4096;
        float* Kg = g_Kt + blk * 4096;
        float* Vg = g_V  + blk * 4096;
        #pragma unroll
        for (int m = 0; m < 4; ++m) {
            float2 a = up2(q01[m]), bb = up2(q23[m]);
            *(float4*)(Qg + (r0+m)*64 + c0) = make_float4(a.x, a.y, bb.x, bb.y);
            *(float4*)(Vg + (r0+m)*64 + c0) = make_float4(vf[m*4], vf[m*4+1], vf[m*4+2], vf[m*4+3]);
        }
        #pragma unroll
        for (int n = 0; n < 4; ++n)
            *(float4*)(Kg + (c0+n)*64 + r0) = make_float4(kf[n], kf[4+n], kf[8+n], kf[12+n]);
    }
    __syncthreads();   /* all reads of sX/sW done; safe to alias */

    /* decayed K and V into smem (alias tiles 0,1) */
    float* sKd = sm;
    float* sVv = sm + TILE_F;
    #pragma unroll
    for (int m = 0; m < 4; ++m) {
        float w = sgp[63 - (r0 + m)];
        *(float4*)(sKd + (r0+m)*SP + c0) = make_float4(kf[m*4]*w, kf[m*4+1]*w, kf[m*4+2]*w, kf[m*4+3]*w);
        *(float4*)(sVv + (r0+m)*SP + c0) = make_float4(vf[m*4], vf[m*4+1], vf[m*4+2], vf[m*4+3]);
    }
    __syncthreads();

    /* A[p][c] = sum_i Kd[i][p] V[i][c] */
    ull a01[4], a23[4];
    #pragma unroll
    for (int m = 0; m < 4; ++m) { a01[m] = 0ull; a23[m] = 0ull; }
    #pragma unroll 4
    for (int i = 0; i < 64; ++i) {
        ull kd[4];
        #pragma unroll
        for (int m = 0; m < 4; ++m) kd[m] = bc2(sKd[i * SP + r0 + m]);
        ulonglong2 vv = *(const ulonglong2*)(sVv + i * SP + c0);
        #pragma unroll
        for (int m = 0; m < 4; ++m) {
            fma2(a01[m], kd[m], vv.x); fma2(a23[m], kd[m], vv.y);
        }
    }
    float* Ag = g_A + blk * 4096;
    #pragma unroll
    for (int m = 0; m < 4; ++m) {
        float2 a = up2(a01[m]), bb = up2(a23[m]);
        *(float4*)(Ag + (r0+m)*64 + c0) = make_float4(a.x, a.y, bb.x, bb.y);
    }
}

/* ---------------- Kernel B: scan over chunks (per state element) --------------- */
__global__ __launch_bounds__(TPB) void kscan() {
    const int e = blockIdx.x * TPB + threadIdx.x;   /* 0..8191 */
    const int b = e >> 12, idx = e & 4095;
    double gd = 1.0;
    #pragma unroll
    for (int n = 0; n < 64; ++n) gd *= GAMMA_D;
    const float d64 = (float)gd;

    const float* Ab = g_A + (size_t)b * NCH * 4096 + idx;
    float*       Sb = g_S + (size_t)b * NCH * 4096 + idx;
    float s = 0.f;
    for (int c = 0; c < NCH; c += 8) {
        float a[8];
        #pragma unroll
        for (int j = 0; j < 8; ++j) a[j] = Ab[(size_t)(c + j) * 4096];
        #pragma unroll
        for (int j = 0; j < 8; ++j) {
            Sb[(size_t)(c + j) * 4096] = s;     /* state at chunk start */
            s = s * d64 + a[j];
        }
    }
}

/* ---- Kernel C: P=Q·K^T (masked), out = P·V + diag(gamma)·Q·S, GN, perm store -- */
__global__ __launch_bounds__(TPB, 3) void kchunkC(const float* __restrict__ gnw,
                                                  const float* __restrict__ gnb,
                                                  float* __restrict__ Out) {
    extern __shared__ float sm[];
    float* sQ  = sm;
    float* sKt = sm + 1 * TILE_F;   /* later reused as sP */
    float* sV  = sm + 2 * TILE_F;
    float* sS  = sm + 3 * TILE_F;
    float* sgp = sm + 4 * TILE_F;

    const int tid = threadIdx.x;
    const int blk = blockIdx.x;
    const int b = blk >> 7, t0 = (blk & 127) << 6;

    const float* Qg = g_Q  + blk * 4096;
    const float* Kg = g_Kt + blk * 4096;
    const float* Vg = g_V  + blk * 4096;
    const float* Sg = g_S  + blk * 4096;

    for (int e = tid; e < 1024; e += TPB) {
        int r = e >> 4, c4 = (e & 15) << 2;
        *(float4*)(sQ  + r * SP + c4) = *(const float4*)(Qg + r * 64 + c4);
        *(float4*)(sKt + r * SP + c4) = *(const float4*)(Kg + r * 64 + c4);
        *(float4*)(sV  + r * SP + c4) = *(const float4*)(Vg + r * 64 + c4);
        *(float4*)(sS  + r * SP + c4) = *(const float4*)(Sg + r * 64 + c4);
    }
    if (tid == 0) {
        double g = 1.0;
        for (int n = 0; n <= 64; ++n) { sgp[n] = (float)g; g *= GAMMA_D; }
    }
    __syncthreads();

    const int ty = tid >> 4, tx = tid & 15;
    const int r0 = ty << 2, c0 = tx << 2;

    const float4 gw4 = *(const float4*)(gnw + c0);
    const float4 gb4 = *(const float4*)(gnb + c0);

    /* P[i][j] = sum_k Q[i][k] Kt[k][j], masked by decay */
    ull p01[4], p23[4];
    #pragma unroll
    for (int m = 0; m < 4; ++m) { p01[m] = 0ull; p23[m] = 0ull; }
    #pragma unroll 4
    for (int k = 0; k < 64; ++k) {
        ull qb[4];
        #pragma unroll
        for (int m = 0; m < 4; ++m) qb[m] = bc2(sQ[(r0 + m) * SP + k]);
        ulonglong2 kt = *(const ulonglong2*)(sKt + k * SP + c0);
        #pragma unroll
        for (int m = 0; m < 4; ++m) {
            fma2(p01[m], qb[m], kt.x); fma2(p23[m], qb[m], kt.y);
        }
    }
    float p[16];
    #pragma unroll
    for (int m = 0; m < 4; ++m) {
        float2 a = up2(p01[m]), bb = up2(p23[m]);
        p[m*4+0]=a.x; p[m*4+1]=a.y; p[m*4+2]=bb.x; p[m*4+3]=bb.y;
    }
    #pragma unroll
    for (int m = 0; m < 4; ++m)
        #pragma unroll
        for (int n = 0; n < 4; ++n) {
            int i = r0 + m, j = c0 + n;
            p[m*4+n] = (i >= j) ? p[m*4+n] * sgp[i - j] : 0.f;
        }
    __syncthreads();                  /* all reads of sKt done */
    float* sP = sKt;
    #pragma unroll
    for (int m = 0; m < 4; ++m)
        *(float4*)(sP + (r0+m)*SP + c0) = make_float4(p[m*4], p[m*4+1], p[m*4+2], p[m*4+3]);
    __syncthreads();

    /* out = P·V + gamma^(i+1) · Q·S */
    ull o1a[4], o1b[4], o2a[4], o2b[4];
    #pragma unroll
    for (int m = 0; m < 4; ++m) { o1a[m]=0ull; o1b[m]=0ull; o2a[m]=0ull; o2b[m]=0ull; }
    #pragma unroll 2
    for (int j = 0; j < 64; ++j) {
        ull pm[4], qm[4];
        #pragma unroll
        for (int m = 0; m < 4; ++m) {
            pm[m] = bc2(sP[(r0 + m) * SP + j]);
            qm[m] = bc2(sQ[(r0 + m) * SP + j]);
        }
        ulonglong2 v = *(const ulonglong2*)(sV + j * SP + c0);
        ulonglong2 s = *(const ulonglong2*)(sS + j * SP + c0);
        #pragma unroll
        for (int m = 0; m < 4; ++m) {
            fma2(o1a[m], pm[m], v.x); fma2(o1b[m], pm[m], v.y);
            fma2(o2a[m], qm[m], s.x); fma2(o2b[m], qm[m], s.y);
        }
    }

    float o[16];
    #pragma unroll
    for (int m = 0; m < 4; ++m) {
        float ge = sgp[r0 + m + 1];
        float2 a1 = up2(o1a[m]), b1 = up2(o1b[m]);
        float2 a2 = up2(o2a[m]), b2 = up2(o2b[m]);
        o[m*4+0] = a1.x + ge * a2.x;
        o[m*4+1] = a1.y + ge * a2.y;
        o[m*4+2] = b1.x + ge * b2.x;
        o[m*4+3] = b1.y + ge * b2.y;
    }

    /* GroupNorm: thread's 4 channels + lane-partner's 4 = one 8-channel group */
    const float gwv[4] = { gw4.x, gw4.y, gw4.z, gw4.w };
    const float gbv[4] = { gb4.x, gb4.y, gb4.z, gb4.w };
    #pragma unroll
    for (int m = 0; m < 4; ++m) {
        float s_ = o[m*4] + o[m*4+1] + o[m*4+2] + o[m*4+3];
        float q_ = o[m*4]*o[m*4] + o[m*4+1]*o[m*4+1] + o[m*4+2]*o[m*4+2] + o[m*4+3]*o[m*4+3];
        s_ += __shfl_xor_sync(0xffffffffu, s_, 1);
        q_ += __shfl_xor_sync(0xffffffffu, q_, 1);
        float mu  = s_ * 0.125f;
        float var = q_ * 0.125f - mu * mu;      /* biased, matches GroupNorm */
        float inv = rsqrtf(var + 1e-6f);
        #pragma unroll
        for (int n = 0; n < 4; ++n)
            o[m*4+n] = (o[m*4+n] - mu) * inv * gwv[n] + gbv[n];
    }

    /* permuted store Out[b][c][t]: per channel, 4 consecutive t as STG.128 */
    float* Ob = Out + (size_t)b * C_DIM * T_SEQ + t0 + r0;
    #pragma unroll
    for (int n = 0; n < 4; ++n)
        *(float4*)(Ob + (size_t)(c0 + n) * T_SEQ) = make_float4(o[n], o[4+n], o[8+n], o[12+n]);
}

extern "C" void kernel_launch(void* const* d_in, const int* in_sizes, int n_in,
                              void* d_out, int out_size) {
    const float* Q_in = (const float*)d_in[0];
    const float* W_Q  = (const float*)d_in[1];
    const float* W_K  = (const float*)d_in[2];
    const float* W_V  = (const float*)d_in[3];
    const float* gnw  = (const float*)d_in[4];
    const float* gnb  = (const float*)d_in[5];
    float* out = (float*)d_out;

    const int smemA = (4 * TILE_F + 72) * (int)sizeof(float);   /* 69920 B */
    const int smemC = (4 * TILE_F + 72) * (int)sizeof(float);   /* 69920 B */
    cudaFuncSetAttribute(kchunkA, cudaFuncAttributeMaxDynamicSharedMemorySize, smemA);
    cudaFuncSetAttribute(kchunkC, cudaFuncAttributeMaxDynamicSharedMemorySize, smemC);

    kchunkA<<<NCHT, TPB, smemA>>>(Q_in, W_Q, W_K, W_V);
    kscan<<<32, TPB>>>();
    kchunkC<<<NCHT, TPB, smemC>>>(gnw, gnb, out);
}